// round 16
// baseline (speedup 1.0000x reference)
#include <cuda_runtime.h>
#include <cuda_fp16.h>
#include <cstdint>

// ---------------------------------------------------------------------------
// Problem constants
// ---------------------------------------------------------------------------
#define BB     16
#define CIN    1024
#define HW     1024      // 32*32
#define CK     256
#define CV     512
#define MTOT   768       // stacked key(256) + value(512) output channels
#define NTILE  4096      // BB * 256 winograd tiles

// shared f16 mma tiling: CTA 128x256, 512 threads (16 warps of 64x32)
#define BM     128
#define BN     256
#define LDH    40        // pitch in halfs (80 B) -> conflict-free frags/LDSM
#define A_BYTES (BM * LDH * 2)          // 10240
#define B_BYTES (BN * LDH * 2)          // 20480
#define STAGE_BYTES (A_BYTES + B_BYTES) // 30720
#define NSTAGE_G 4
#define SMEM_GEMM (128 + NSTAGE_G * STAGE_BYTES)  // 123008
#define SMEM_TOTAL (3 * STAGE_BYTES)              // cp.async kernels (92160)

#define KITERS_WG   32    // 1024 / 32
#define KITERS_SC   8     // 256 / 32
#define KITERS_OUT  32    // 1024 / 32

// blocked U/V strides (pitch-40 rows, smem-image layout)
#define U_STRIDE  ((size_t)16 * 32 * MTOT  * LDH)   // per-branch U halfs
#define V_STRIDE  ((size_t)16 * 32 * NTILE * LDH)   // per-branch V halfs
#define M_STRIDE  ((size_t)16 * MTOT * NTILE)       // per-branch M halfs

// ---------------------------------------------------------------------------
// Scratch (device globals; no allocation allowed). All accessed ONLY from
// device code (host passes `which` flags, never symbol addresses).
// ---------------------------------------------------------------------------
__device__ __half g_srcT0[BB * HW * CIN];    // f16 src_temp  [b][pix][ci]
__device__ __half g_srcT1[BB * HW * CIN];    // f16 src_search
__device__ __half g_U [2 * 16 * 32 * MTOT  * LDH]; // [br][t][kt][co][40]
__device__ __half g_V [2 * 16 * 32 * NTILE * LDH]; // [br][t][kt][bt][40]
__device__ __half g_Mh[2 * 16 * MTOT * NTILE];     // [br][t][co][bt] f16
__device__ __half g_mkh[BB * CK * HW];       // m_key   [b][c][pix] f16
__device__ __half g_qkh[BB * CK * HW];       // q_key   [b][c][pix] f16
__device__ __half g_mkT[BB * HW * CK];       // m_key   [b][m][c]   f16
__device__ __half g_qkT[BB * HW * CK];       // q_key   [b][q][c]   f16
__device__ __half g_mvh[BB * CV * HW];       // m_value [b][c][m]   f16
__device__ __half g_E  [BB * HW * HW];       // exp(S)  [b][q][m]   f16
__device__ float  g_rsum[BB * HW];           // row sum of exp (atomic acc)

// ---------------------------------------------------------------------------
// async-copy / ldmatrix helpers
// ---------------------------------------------------------------------------
__device__ __forceinline__ void cp_async16z(uint32_t s, const void* g, int sz) {
    asm volatile("cp.async.cg.shared.global [%0], [%1], 16, %2;"
                 :: "r"(s), "l"(g), "r"(sz));
}
__device__ __forceinline__ void cp_commit() { asm volatile("cp.async.commit_group;"); }
__device__ __forceinline__ void cp_wait1()  { asm volatile("cp.async.wait_group 1;"); }

__device__ __forceinline__ void mbar_init(uint32_t a, uint32_t cnt) {
    asm volatile("mbarrier.init.shared.b64 [%0], %1;" :: "r"(a), "r"(cnt) : "memory");
}
__device__ __forceinline__ void mbar_expect_tx(uint32_t a, uint32_t bytes) {
    asm volatile("mbarrier.arrive.expect_tx.shared.b64 _, [%0], %1;"
                 :: "r"(a), "r"(bytes) : "memory");
}
__device__ __forceinline__ void bulk_g2s(uint32_t dst, const void* src,
                                         uint32_t bytes, uint32_t mbar) {
    asm volatile("cp.async.bulk.shared::cluster.global.mbarrier::complete_tx::bytes "
                 "[%0], [%1], %2, [%3];"
                 :: "r"(dst), "l"(src), "r"(bytes), "r"(mbar) : "memory");
}
__device__ __forceinline__ void mbar_wait(uint32_t a, uint32_t parity) {
    uint32_t done;
    asm volatile("{\n\t.reg .pred p;\n\t"
        "mbarrier.try_wait.parity.acquire.cta.shared::cta.b64 p, [%1], %2;\n\t"
        "selp.b32 %0, 1, 0, p;\n\t}" : "=r"(done) : "r"(a), "r"(parity) : "memory");
    if (!done) {
        asm volatile("{\n\t.reg .pred P1;\n\t"
            "WL_%=:\n\t"
            "mbarrier.try_wait.parity.acquire.cta.shared::cta.b64 P1, [%0], %1, 0x989680;\n\t"
            "@P1 bra.uni WD_%=;\n\t"
            "bra.uni WL_%=;\n\t"
            "WD_%=:\n\t}" :: "r"(a), "r"(parity) : "memory");
    }
}
__device__ __forceinline__ void ldsm_x4(uint32_t& r0, uint32_t& r1,
                                        uint32_t& r2, uint32_t& r3, uint32_t addr) {
    asm volatile("ldmatrix.sync.aligned.m8n8.x4.shared.b16 {%0,%1,%2,%3}, [%4];"
                 : "=r"(r0), "=r"(r1), "=r"(r2), "=r"(r3) : "r"(addr));
}

#define MMA_F16(acc, a, bf)                                                   \
    asm volatile(                                                             \
        "mma.sync.aligned.m16n8k16.row.col.f32.f16.f16.f32 "                  \
        "{%0,%1,%2,%3}, {%4,%5,%6,%7}, {%8,%9}, {%0,%1,%2,%3};"               \
        : "+f"((acc)[0]), "+f"((acc)[1]), "+f"((acc)[2]), "+f"((acc)[3])      \
        : "r"((a)[0]), "r"((a)[1]), "r"((a)[2]), "r"((a)[3]),                 \
          "r"((bf)[0]), "r"((bf)[1]))

// ldmatrix-based fragment load + mma for one 64x32 warp tile, one 32-K tile.
#define MMA_TILE_LDSM(acc, sAu, sBu, wm, wn, sub, seg)                        \
    do {                                                                      \
        const int _arow = ((seg) & 1) * 8 + (sub);                            \
        const int _akof = ((seg) >> 1) * 8;                                   \
        const int _bnt  = (seg) >> 1;                                         \
        const int _bkof = ((seg) & 1) * 8;                                    \
        _Pragma("unroll")                                                     \
        for (int s = 0; s < 2; ++s) {                                         \
            const int k16 = s * 16;                                           \
            uint32_t a[4][4], bf[4][2];                                       \
            _Pragma("unroll")                                                 \
            for (int mt = 0; mt < 4; ++mt)                                    \
                ldsm_x4(a[mt][0], a[mt][1], a[mt][2], a[mt][3],               \
                    (sAu) + (uint32_t)((((wm) + mt * 16 + _arow) * LDH        \
                                        + k16 + _akof) * 2));                 \
            _Pragma("unroll")                                                 \
            for (int p = 0; p < 2; ++p)                                       \
                ldsm_x4(bf[p*2][0], bf[p*2][1], bf[p*2+1][0], bf[p*2+1][1],   \
                    (sBu) + (uint32_t)((((wn) + (p * 2 + _bnt) * 8 + (sub))   \
                                        * LDH + k16 + _bkof) * 2));           \
            _Pragma("unroll")                                                 \
            for (int mt = 0; mt < 4; ++mt)                                    \
                _Pragma("unroll")                                             \
                for (int nt = 0; nt < 4; ++nt)                                \
                    MMA_F16(acc[mt][nt], a[mt], bf[nt]);                      \
        }                                                                     \
    } while (0)

// ---------------------------------------------------------------------------
// Pre-pass: transpose + f16 src, BOTH branches: [b][ci][pix] -> [b][pix][ci]
// ---------------------------------------------------------------------------
__global__ void transpose_src(const float* __restrict__ s0,
                              const float* __restrict__ s1)
{
    __shared__ float t[32][33];
    int b = blockIdx.z & 15;
    int which = blockIdx.z >> 4;
    const float* src = which ? s1 : s0;
    int pix0 = blockIdx.x * 32, ci0 = blockIdx.y * 32;
    const float* s = src + ((size_t)b * CIN + ci0) * HW + pix0;
    for (int i = threadIdx.y; i < 32; i += 8)
        t[i][threadIdx.x] = s[(size_t)i * HW + threadIdx.x];   // t[ci][pix]
    __syncthreads();
    __half* d = (which ? g_srcT1 : g_srcT0) + ((size_t)b * HW + pix0) * CIN + ci0;
    for (int i = threadIdx.y; i < 32; i += 8)
        d[(size_t)i * CIN + threadIdx.x] = __float2half_rn(t[threadIdx.x][i]);
}

// ---------------------------------------------------------------------------
// Winograd weight transform, BOTH branches: U = G g G^T per (br, co, ci).
// Output BLOCKED: U[br][t][kt][co][40]. Also zeroes g_rsum (ordered before
// scores_tc on the stream).
// ---------------------------------------------------------------------------
__global__ void wg_w(const float* __restrict__ wk_m, const float* __restrict__ wv_m,
                     const float* __restrict__ wk_q, const float* __restrict__ wv_q)
{
    int idx = blockIdx.x * blockDim.x + threadIdx.x;
    if (idx < BB * HW) g_rsum[idx] = 0.f;
    if (idx >= 2 * MTOT * CIN) return;
    int which = (idx >= MTOT * CIN);
    int r2 = idx - which * (MTOT * CIN);
    int co = r2 / CIN;
    int ci = r2 - co * CIN;
    const float* wk = which ? wk_q : wk_m;
    const float* wv = which ? wv_q : wv_m;
    __half* __restrict__ U = g_U + (size_t)which * U_STRIDE;
    const int kt = ci >> 5, kk = ci & 31;

    const float* g = (co < CK) ? (wk + ((size_t)co * CIN + ci) * 9)
                               : (wv + ((size_t)(co - CK) * CIN + ci) * 9);
    float gr[3][3];
#pragma unroll
    for (int r = 0; r < 9; ++r) gr[r / 3][r % 3] = g[r];
    float t[4][3];
#pragma unroll
    for (int j = 0; j < 3; ++j) {
        t[0][j] = gr[0][j];
        t[1][j] = 0.5f * (gr[0][j] + gr[1][j] + gr[2][j]);
        t[2][j] = 0.5f * (gr[0][j] - gr[1][j] + gr[2][j]);
        t[3][j] = gr[2][j];
    }
#pragma unroll
    for (int i = 0; i < 4; ++i) {
        float u0 = t[i][0];
        float u1 = 0.5f * (t[i][0] + t[i][1] + t[i][2]);
        float u2 = 0.5f * (t[i][0] - t[i][1] + t[i][2]);
        float u3 = t[i][2];
        const float uv[4] = {u0, u1, u2, u3};
#pragma unroll
        for (int j = 0; j < 4; ++j)
            U[(((size_t)(i * 4 + j) * 32 + kt) * MTOT + co) * LDH + kk] =
                __float2half_rn(uv[j]);
    }
}

// ---------------------------------------------------------------------------
// Winograd input transform, BOTH branches: V = B^T d B per (br, b, tile, ci).
// Output BLOCKED: V[br][t][kt][bt][40]. grid (256 tiles, 32). Zero-pad halo.
// ---------------------------------------------------------------------------
__global__ __launch_bounds__(256)
void wg_d()
{
    const int b     = blockIdx.y & 15;
    const int which = blockIdx.y >> 4;
    const __half* __restrict__ srcT = which ? g_srcT1 : g_srcT0;
    __half* __restrict__ V = g_V + (size_t)which * V_STRIDE;
    const int tile = blockIdx.x;
    const int ty = tile >> 4, tx = tile & 15;
    const int oy = 2 * ty, ox = 2 * tx;
    const int bt = b * 256 + tile;
    const __half* sb = srcT + (size_t)b * (HW * CIN);

#pragma unroll
    for (int pass = 0; pass < 2; ++pass) {
        int ci = (threadIdx.x + pass * 256) * 2;
        const int kt = ci >> 5, kk = ci & 31;
        float2 d[4][4];
#pragma unroll
        for (int i = 0; i < 4; ++i) {
            int iy = oy - 1 + i;
#pragma unroll
            for (int j = 0; j < 4; ++j) {
                int ix = ox - 1 + j;
                if ((unsigned)iy < 32u && (unsigned)ix < 32u) {
                    __half2 h = *reinterpret_cast<const __half2*>(
                        &sb[(size_t)(iy * 32 + ix) * CIN + ci]);
                    d[i][j] = __half22float2(h);
                } else {
                    d[i][j] = make_float2(0.f, 0.f);
                }
            }
        }
        float2 r[4][4];
#pragma unroll
        for (int j = 0; j < 4; ++j) {
            r[0][j] = make_float2(d[0][j].x - d[2][j].x, d[0][j].y - d[2][j].y);
            r[1][j] = make_float2(d[1][j].x + d[2][j].x, d[1][j].y + d[2][j].y);
            r[2][j] = make_float2(d[2][j].x - d[1][j].x, d[2][j].y - d[1][j].y);
            r[3][j] = make_float2(d[1][j].x - d[3][j].x, d[1][j].y - d[3][j].y);
        }
#pragma unroll
        for (int i = 0; i < 4; ++i) {
            float2 v[4];
            v[0] = make_float2(r[i][0].x - r[i][2].x, r[i][0].y - r[i][2].y);
            v[1] = make_float2(r[i][1].x + r[i][2].x, r[i][1].y + r[i][2].y);
            v[2] = make_float2(r[i][2].x - r[i][1].x, r[i][2].y - r[i][1].y);
            v[3] = make_float2(r[i][1].x - r[i][3].x, r[i][1].y - r[i][3].y);
#pragma unroll
            for (int j = 0; j < 4; ++j) {
                *reinterpret_cast<__half2*>(
                    &V[(((size_t)(i * 4 + j) * 32 + kt) * NTILE + bt) * LDH + kk]) =
                    __floats2half2_rn(v[j].x, v[j].y);
            }
        }
    }
}

// ---------------------------------------------------------------------------
// Winograd GEMM, BOTH branches: M[t][co][n] = sum_ci U*V, f16 mma.
// Bulk-copy + mbarrier 4-stage pipeline; ldmatrix fragment loads.
// grid (16 n-tiles, 12, 16 t). 512 thr, warp tile 64x32.
// ---------------------------------------------------------------------------
__global__ __launch_bounds__(512, 1)
void wg_gemm()
{
    extern __shared__ char sm[];
    const int which = blockIdx.y / 6;
    const int tid  = threadIdx.x;
    const int warp = tid >> 5, lane = tid & 31;
    const int grp  = lane >> 2, tig = lane & 3;
    const int sub  = lane & 7, seg = lane >> 3;
    const int wm   = (warp >> 3) * 64;      // 0 / 64
    const int wn   = (warp & 7) * 32;       // 0..224

    const int n0  = blockIdx.x * BN;
    const int co0 = (blockIdx.y % 6) * BM;
    const int t   = blockIdx.z;
    const __half* Ub = g_U + (size_t)which * U_STRIDE + (size_t)t * 32 * MTOT * LDH;
    const __half* Vb = g_V + (size_t)which * V_STRIDE + (size_t)t * 32 * NTILE * LDH;
    __half* __restrict__ Mh = g_Mh + (size_t)which * M_STRIDE;

    const uint32_t smem_u = (uint32_t)__cvta_generic_to_shared(sm);
    const uint32_t mb0    = smem_u;            // 4 mbarriers at +0,+8,+16,+24
    const uint32_t stg0   = smem_u + 128;

    if (tid == 0) {
        mbar_init(mb0 + 0, 1);
        mbar_init(mb0 + 8, 1);
        mbar_init(mb0 + 16, 1);
        mbar_init(mb0 + 24, 1);
    }
    __syncthreads();

    auto issue = [&](int kt, int buf) {
        const uint32_t mbar = mb0 + buf * 8;
        const uint32_t sA = stg0 + (uint32_t)buf * STAGE_BYTES;
        mbar_expect_tx(mbar, STAGE_BYTES);
        bulk_g2s(sA, Ub + ((size_t)kt * MTOT + co0) * LDH, A_BYTES, mbar);
        bulk_g2s(sA + A_BYTES, Vb + ((size_t)kt * NTILE + n0) * LDH, B_BYTES, mbar);
    };
    if (tid == 0) { issue(0, 0); issue(1, 1); issue(2, 2); issue(3, 3); }

    float acc[4][4][4];
#pragma unroll
    for (int mt = 0; mt < 4; ++mt)
#pragma unroll
        for (int nt = 0; nt < 4; ++nt)
#pragma unroll
            for (int c = 0; c < 4; ++c) acc[mt][nt][c] = 0.f;

    for (int kt = 0; kt < KITERS_WG; ++kt) {
        const int buf = kt % NSTAGE_G;
        mbar_wait(mb0 + buf * 8, (kt / NSTAGE_G) & 1);

        const uint32_t sAu = stg0 + (uint32_t)buf * STAGE_BYTES;
        const uint32_t sBu = sAu + A_BYTES;
        MMA_TILE_LDSM(acc, sAu, sBu, wm, wn, sub, seg);

        __syncthreads();                       // all warps done with buf
        if (kt + NSTAGE_G < KITERS_WG && tid == 0) issue(kt + NSTAGE_G, buf);
    }

#pragma unroll
    for (int mt = 0; mt < 4; ++mt) {
        int r0 = co0 + wm + mt * 16 + grp;
        int r1 = r0 + 8;
        __half* d0 = Mh + ((size_t)t * MTOT + r0) * NTILE + n0;
        __half* d1 = Mh + ((size_t)t * MTOT + r1) * NTILE + n0;
#pragma unroll
        for (int nt = 0; nt < 4; ++nt) {
            int col = wn + nt * 8 + 2 * tig;
            *reinterpret_cast<__half2*>(&d0[col]) =
                __floats2half2_rn(acc[mt][nt][0], acc[mt][nt][1]);
            *reinterpret_cast<__half2*>(&d1[col]) =
                __floats2half2_rn(acc[mt][nt][2], acc[mt][nt][3]);
        }
    }
}

// ---------------------------------------------------------------------------
// Winograd output transform, BOTH branches: Y = A^T m A (+bias), scatter.
// ---------------------------------------------------------------------------
__global__ __launch_bounds__(256)
void wg_out(const float* __restrict__ bk_m, const float* __restrict__ bv_m,
            const float* __restrict__ bk_q, const float* __restrict__ bv_q,
            float* __restrict__ out)
{
    const int which = blockIdx.x >> 4;
    const int bt = (blockIdx.x & 15) * 256 + threadIdx.x;
    const int co = blockIdx.y;
    const int b    = bt >> 8;
    const int tile = bt & 255;
    const int ty = tile >> 4, tx = tile & 15;
    const int pix = (2 * ty) * 32 + 2 * tx;
    const __half* Mh = g_Mh + (size_t)which * M_STRIDE;
    const float* bias_k = which ? bk_q : bk_m;
    const float* bias_v = which ? bv_q : bv_m;

    float m[4][4];
#pragma unroll
    for (int i = 0; i < 4; ++i)
#pragma unroll
        for (int j = 0; j < 4; ++j)
            m[i][j] = __half2float(Mh[((size_t)(i * 4 + j) * MTOT + co) * NTILE + bt]);

    float s0[4], s1[4];
#pragma unroll
    for (int j = 0; j < 4; ++j) {
        s0[j] = m[0][j] + m[1][j] + m[2][j];
        s1[j] = m[1][j] - m[2][j] - m[3][j];
    }
    float y00 = s0[0] + s0[1] + s0[2];
    float y01 = s0[1] - s0[2] - s0[3];
    float y10 = s1[0] + s1[1] + s1[2];
    float y11 = s1[1] - s1[2] - s1[3];

    if (co < CK) {
        float bia = bias_k[co];
        __half* d = (which ? g_qkh : g_mkh) + ((size_t)b * CK + co) * HW;
        *reinterpret_cast<__half2*>(&d[pix])      = __floats2half2_rn(y00 + bia, y01 + bia);
        *reinterpret_cast<__half2*>(&d[pix + 32]) = __floats2half2_rn(y10 + bia, y11 + bia);
    } else {
        int cv = co - CK;
        float bia = bias_v[cv];
        if (which) {
            float* d = out + (size_t)b * (2 * CV * HW) + (size_t)(CV + cv) * HW;
            *reinterpret_cast<float2*>(&d[pix])      = make_float2(y00 + bia, y01 + bia);
            *reinterpret_cast<float2*>(&d[pix + 32]) = make_float2(y10 + bia, y11 + bia);
        } else {
            __half* d = g_mvh + ((size_t)b * CV + cv) * HW;
            *reinterpret_cast<__half2*>(&d[pix])      = __floats2half2_rn(y00 + bia, y01 + bia);
            *reinterpret_cast<__half2*>(&d[pix + 32]) = __floats2half2_rn(y10 + bia, y11 + bia);
        }
    }
}

// ---------------------------------------------------------------------------
// Key transpose f16, BOTH branches: [b][c][pix] -> [b][pix][c]
// ---------------------------------------------------------------------------
__global__ void transpose_kh()
{
    __shared__ __half t[32][34];
    int b = blockIdx.z & 15;
    int which = blockIdx.z >> 4;
    const __half* in = which ? g_qkh : g_mkh;
    __half* outp     = which ? g_qkT : g_mkT;
    int pix0 = blockIdx.x * 32, c0 = blockIdx.y * 32;
    const __half* s = in + ((size_t)b * CK + c0) * HW + pix0;
    for (int i = threadIdx.y; i < 32; i += 8)
        t[i][threadIdx.x] = s[(size_t)i * HW + threadIdx.x];   // t[c][pix]
    __syncthreads();
    __half* d = outp + ((size_t)b * HW + pix0) * CK + c0;
    for (int i = threadIdx.y; i < 32; i += 8)
        d[(size_t)i * CK + threadIdx.x] = t[threadIdx.x][i];
}

// ---------------------------------------------------------------------------
// Scores + exp fused (f16 mma, 512 thr, ldmatrix):
// E[b][q][m] = exp( (1/16) * sum_c qkT[q][c]*mkT[m][c] )   (no max-sub:
// |S| <= ~5 statistically, exp cannot overflow), and g_rsum[b][q] +=
// partial row sums via atomics. grid (64, 8).
// ---------------------------------------------------------------------------
__global__ __launch_bounds__(512, 1)
void scores_tc()
{
    extern __shared__ char sm[];
    const int tid  = threadIdx.x;
    const int warp = tid >> 5, lane = tid & 31;
    const int grp  = lane >> 2, tig = lane & 3;
    const int sub  = lane & 7, seg = lane >> 3;
    const int wm   = (warp >> 3) * 64;
    const int wn   = (warp & 7) * 32;

    const int b  = blockIdx.x >> 2;
    const int m0 = (blockIdx.x & 3) * BN;
    const int q0 = blockIdx.y * BM;
    const __half* qkT = g_qkT + (size_t)b * (HW * CK);
    const __half* mkT = g_mkT + (size_t)b * (HW * CK);

    const uint32_t smem_u = (uint32_t)__cvta_generic_to_shared(sm);

    float acc[4][4][4];
#pragma unroll
    for (int mt = 0; mt < 4; ++mt)
#pragma unroll
        for (int nt = 0; nt < 4; ++nt)
#pragma unroll
            for (int c = 0; c < 4; ++c) acc[mt][nt][c] = 0.f;

    const int am = tid >> 2, aq = tid & 3;
    const int bn = tid >> 1, bh = tid & 1;
    auto issue = [&](int kt, int buf) {
        const uint32_t sA = smem_u + (uint32_t)buf * STAGE_BYTES;
        const uint32_t sB = sA + A_BYTES;
        cp_async16z(sA + (uint32_t)(am * (LDH * 2) + aq * 16),
                    qkT + (size_t)(q0 + am) * CK + kt * 32 + aq * 8, 16);
        const __half* bbase = mkT + (size_t)(m0 + bn) * CK + kt * 32 + bh * 16;
        const uint32_t rb = (uint32_t)(bn * (LDH * 2) + bh * 32);
#pragma unroll
        for (int j = 0; j < 2; ++j)
            cp_async16z(sB + rb + j * 16, bbase + j * 8, 16);
    };

    issue(0, 0); cp_commit();
    issue(1, 1); cp_commit();

    int buf = 0;
    for (int kt = 0; kt < KITERS_SC; ++kt) {
        cp_wait1();
        __syncthreads();
        if (kt + 2 < KITERS_SC) issue(kt + 2, (buf + 2) % 3);
        cp_commit();

        const uint32_t sAu = smem_u + (uint32_t)buf * STAGE_BYTES;
        const uint32_t sBu = sAu + A_BYTES;
        MMA_TILE_LDSM(acc, sAu, sBu, wm, wn, sub, seg);
        __syncthreads();
        buf = (buf + 1) % 3;
    }

    const float scale = 0.0625f;   // 1/sqrt(256)
#pragma unroll
    for (int mt = 0; mt < 4; ++mt) {
        int r0 = q0 + wm + mt * 16 + grp;
        int r1 = r0 + 8;
        __half* e0 = g_E + (size_t)b * (HW * HW) + (size_t)r0 * HW + m0;
        __half* e1 = g_E + (size_t)b * (HW * HW) + (size_t)r1 * HW + m0;
        float sum0 = 0.f, sum1 = 0.f;
#pragma unroll
        for (int nt = 0; nt < 4; ++nt) {
            int col = wn + nt * 8 + 2 * tig;
            float ea = __expf(acc[mt][nt][0] * scale);
            float eb = __expf(acc[mt][nt][1] * scale);
            float ec = __expf(acc[mt][nt][2] * scale);
            float ed = __expf(acc[mt][nt][3] * scale);
            *reinterpret_cast<__half2*>(&e0[col]) = __floats2half2_rn(ea, eb);
            *reinterpret_cast<__half2*>(&e1[col]) = __floats2half2_rn(ec, ed);
            sum0 += ea + eb;
            sum1 += ec + ed;
        }
        // reduce over the 4 tig lanes covering this row's columns
        sum0 += __shfl_xor_sync(0xFFFFFFFFu, sum0, 1);
        sum0 += __shfl_xor_sync(0xFFFFFFFFu, sum0, 2);
        sum1 += __shfl_xor_sync(0xFFFFFFFFu, sum1, 1);
        sum1 += __shfl_xor_sync(0xFFFFFFFFu, sum1, 2);
        if (tig == 0) {
            atomicAdd(&g_rsum[b * HW + r0], sum0);
            atomicAdd(&g_rsum[b * HW + r1], sum1);
        }
    }
}

// ---------------------------------------------------------------------------
// Readout (f16 mma, 512 thr, ldmatrix): out = (sum_m mvh*E) / rowsum
// ---------------------------------------------------------------------------
__global__ __launch_bounds__(512, 1)
void out_tc(float* __restrict__ out)
{
    extern __shared__ char sm[];
    const int tid  = threadIdx.x;
    const int warp = tid >> 5, lane = tid & 31;
    const int grp  = lane >> 2, tig = lane & 3;
    const int sub  = lane & 7, seg = lane >> 3;
    const int wm   = (warp >> 3) * 64;
    const int wn   = (warp & 7) * 32;

    const int b  = blockIdx.x >> 2;
    const int q0 = (blockIdx.x & 3) * BN;
    const int c0 = blockIdx.y * BM;
    const __half* mvh = g_mvh + (size_t)b * (CV * HW);
    const __half* E   = g_E   + (size_t)b * (HW * HW);

    const uint32_t smem_u = (uint32_t)__cvta_generic_to_shared(sm);

    float acc[4][4][4];
#pragma unroll
    for (int mt = 0; mt < 4; ++mt)
#pragma unroll
        for (int nt = 0; nt < 4; ++nt)
#pragma unroll
            for (int c = 0; c < 4; ++c) acc[mt][nt][c] = 0.f;

    const int am = tid >> 2, aq = tid & 3;
    const int bn = tid >> 1, bh = tid & 1;
    auto issue = [&](int kt, int buf) {
        const uint32_t sA = smem_u + (uint32_t)buf * STAGE_BYTES;
        const uint32_t sB = sA + A_BYTES;
        cp_async16z(sA + (uint32_t)(am * (LDH * 2) + aq * 16),
                    mvh + (size_t)(c0 + am) * HW + kt * 32 + aq * 8, 16);
        const __half* bbase = E + (size_t)(q0 + bn) * HW + kt * 32 + bh * 16;
        const uint32_t rb = (uint32_t)(bn * (LDH * 2) + bh * 32);
#pragma unroll
        for (int j = 0; j < 2; ++j)
            cp_async16z(sB + rb + j * 16, bbase + j * 8, 16);
    };

    issue(0, 0); cp_commit();
    issue(1, 1); cp_commit();

    int buf = 0;
    for (int kt = 0; kt < KITERS_OUT; ++kt) {
        cp_wait1();
        __syncthreads();
        if (kt + 2 < KITERS_OUT) issue(kt + 2, (buf + 2) % 3);
        cp_commit();

        const uint32_t sAu = smem_u + (uint32_t)buf * STAGE_BYTES;
        const uint32_t sBu = sAu + A_BYTES;
        MMA_TILE_LDSM(acc, sAu, sBu, wm, wn, sub, seg);
        __syncthreads();
        buf = (buf + 1) % 3;
    }

    const float* rs = g_rsum + (size_t)b * HW;
#pragma unroll
    for (int mt = 0; mt < 4; ++mt) {
        int r0 = c0 + wm + mt * 16 + grp;
        int r1 = r0 + 8;
        float* d0 = out + (size_t)b * (2 * CV * HW) + (size_t)r0 * HW;
        float* d1 = out + (size_t)b * (2 * CV * HW) + (size_t)r1 * HW;
#pragma unroll
        for (int nt = 0; nt < 4; ++nt) {
            int col = q0 + wn + nt * 8 + 2 * tig;
            float2 sv = *reinterpret_cast<const float2*>(&rs[col]);
            float rx = 1.0f / sv.x;
            float ry = 1.0f / sv.y;
            *reinterpret_cast<float2*>(&d0[col]) =
                make_float2(acc[mt][nt][0] * rx, acc[mt][nt][1] * ry);
            *reinterpret_cast<float2*>(&d1[col]) =
                make_float2(acc[mt][nt][2] * rx, acc[mt][nt][3] * ry);
        }
    }
}

// ---------------------------------------------------------------------------
// Launch
// ---------------------------------------------------------------------------
extern "C" void kernel_launch(void* const* d_in, const int* in_sizes, int n_in,
                              void* d_out, int out_size)
{
    const float* src_t = (const float*)d_in[0];
    const float* src_s = (const float*)d_in[1];
    const float* wk_m  = (const float*)d_in[2];
    const float* bk_m  = (const float*)d_in[3];
    const float* wv_m  = (const float*)d_in[4];
    const float* bv_m  = (const float*)d_in[5];
    const float* wk_q  = (const float*)d_in[6];
    const float* bk_q  = (const float*)d_in[7];
    const float* wv_q  = (const float*)d_in[8];
    const float* bv_q  = (const float*)d_in[9];
    float* out = (float*)d_out;

    cudaFuncSetAttribute(wg_gemm,   cudaFuncAttributeMaxDynamicSharedMemorySize, SMEM_GEMM);
    cudaFuncSetAttribute(scores_tc, cudaFuncAttributeMaxDynamicSharedMemorySize, SMEM_TOTAL);
    cudaFuncSetAttribute(out_tc,    cudaFuncAttributeMaxDynamicSharedMemorySize, SMEM_TOTAL);

    // 0. transpose + f16 sources (both branches)
    {
        dim3 grid(32, 32, 32);
        dim3 blk(32, 8);
        transpose_src<<<grid, blk>>>(src_t, src_s);
    }
    // 1. winograd weight transforms (both branches) + g_rsum zero
    {
        int n = 2 * MTOT * CIN;
        wg_w<<<(n + 255) / 256, 256>>>(wk_m, wv_m, wk_q, wv_q);
    }
    // 2. winograd conv: input transform, GEMM (bulk + ldmatrix), output
    {
        dim3 dgrid(256, 32);
        wg_d<<<dgrid, 256>>>();

        dim3 ggrid(16, 12, 16);
        wg_gemm<<<ggrid, 512, SMEM_GEMM>>>();

        dim3 ogrid(32, MTOT);
        wg_out<<<ogrid, 256>>>(bk_m, bv_m, bk_q, bv_q, out);
    }
    // 3. key transposes -> [b][pix][c] (both branches)
    {
        dim3 grid(32, 8, 32);
        dim3 blk(32, 8);
        transpose_kh<<<grid, blk>>>();
    }
    // 4. attention scores + exp + rowsum (fused), E[b][q][m] f16
    {
        dim3 grid(64, 8);
        scores_tc<<<grid, 512, SMEM_TOTAL>>>();
    }
    // 5. readout -> out channels [0, 512)
    {
        dim3 grid(64, 4);
        out_tc<<<grid, 512, SMEM_TOTAL>>>(out);
    }
}